// round 8
// baseline (speedup 1.0000x reference)
#include <cuda_runtime.h>
#include <cuda_bf16.h>
#include <cstdint>

#define THREADS 768
#define TILE    192

// bf16 tiles, row stride in BYTES (stride/4 mod 32 = 20 -> 8-row LDSM conflict-free)
#define ASTR1 464   // A1: 192 x [xhi(112) | xlo(112)]
#define BSTR1 464   // B1: 80  x [whi(112) | wlo(112)]
#define ASTR2 336   // A2: 192 x [hhi(80)  | hlo(80)]
#define BSTR2 336   // B2: 64  x [whi(80)  | wlo(80)]

#define OFF_A1  0         // 192*464 = 89088
#define OFF_A2  89088     // 192*336 = 64512 -> 153600
#define OFF_B1  153600    // 80*464  = 37120 -> 190720
#define OFF_B2  190720    // 64*336  = 21504 -> 212224
#define OFF_B1S 212224    // 80 f32
#define OFF_B2S 212544    // 64 f32
#define SMEM_TOTAL 212800

__device__ __forceinline__ uint32_t smem_u32(const void* p) {
    uint32_t a;
    asm("{ .reg .u64 t; cvta.to.shared.u64 t, %1; cvt.u32.u64 %0, t; }" : "=r"(a) : "l"(p));
    return a;
}

__device__ __forceinline__ void split_pack(float x0, float x1, uint32_t& hi, uint32_t& lo) {
    uint16_t h0 = __bfloat16_as_ushort(__float2bfloat16_rn(x0));
    uint16_t h1 = __bfloat16_as_ushort(__float2bfloat16_rn(x1));
    float f0 = __uint_as_float((uint32_t)h0 << 16);
    float f1 = __uint_as_float((uint32_t)h1 << 16);
    uint16_t l0 = __bfloat16_as_ushort(__float2bfloat16_rn(x0 - f0));
    uint16_t l1 = __bfloat16_as_ushort(__float2bfloat16_rn(x1 - f1));
    hi = (uint32_t)h0 | ((uint32_t)h1 << 16);
    lo = (uint32_t)l0 | ((uint32_t)l1 << 16);
}

__device__ __forceinline__ float fast_tanh(float x) {
    float e = __expf(2.0f * x);
    return 1.0f - __fdividef(2.0f, e + 1.0f);
}

__device__ __forceinline__ void ldsm_x4(uint32_t& r0, uint32_t& r1, uint32_t& r2, uint32_t& r3,
                                        uint32_t addr) {
    asm volatile("ldmatrix.sync.aligned.m8n8.x4.shared.b16 {%0,%1,%2,%3}, [%4];"
        : "=r"(r0), "=r"(r1), "=r"(r2), "=r"(r3) : "r"(addr));
}
__device__ __forceinline__ void ldsm_x2(uint32_t& r0, uint32_t& r1, uint32_t addr) {
    asm volatile("ldmatrix.sync.aligned.m8n8.x2.shared.b16 {%0,%1}, [%2];"
        : "=r"(r0), "=r"(r1) : "r"(addr));
}

__device__ __forceinline__ void mma16816(float* d, uint32_t a0, uint32_t a1, uint32_t a2,
                                         uint32_t a3, uint32_t b0, uint32_t b1) {
    asm volatile(
        "mma.sync.aligned.m16n8k16.row.col.f32.bf16.bf16.f32 "
        "{%0,%1,%2,%3}, {%4,%5,%6,%7}, {%8,%9}, {%0,%1,%2,%3};"
        : "+f"(d[0]), "+f"(d[1]), "+f"(d[2]), "+f"(d[3])
        : "r"(a0), "r"(a1), "r"(a2), "r"(a3), "r"(b0), "r"(b1));
}

extern __shared__ char smem[];

__global__ void __launch_bounds__(THREADS, 1)
edge_mlp_mma(const float* __restrict__ dstf, const float* __restrict__ dsth,
             const float* __restrict__ srcf, const float* __restrict__ srch,
             const float* __restrict__ ef,
             const float* __restrict__ W1, const float* __restrict__ b1,
             const float* __restrict__ W2, const float* __restrict__ b2,
             float* __restrict__ out, int E)
{
    const uint32_t sb = smem_u32(smem);
    const int tid  = threadIdx.x;
    const int lane = tid & 31;
    const int warp = tid >> 5;            // 0..23
    float* b1s = (float*)(smem + OFF_B1S);
    float* b2s = (float*)(smem + OFF_B2S);

    // ---- one-time zero (covers all k-pads; stale rows in partial tiles are
    //      finite garbage whose outputs are never stored) ----
    for (int i = tid; i < OFF_B1S / 4; i += THREADS) ((uint32_t*)smem)[i] = 0u;
    __syncthreads();

    // ---- stage split weights ----
    for (int i = tid; i < 80 * 56; i += THREADS) {        // W1: 56 k-pairs/row
        int n = i / 56, c2 = (i - n * 56) * 2;
        float w0 = (c2     < 97) ? W1[n * 97 + c2]     : 0.0f;
        float w1 = (c2 + 1 < 97) ? W1[n * 97 + c2 + 1] : 0.0f;
        uint32_t hi, lo; split_pack(w0, w1, hi, lo);
        *(uint32_t*)(smem + OFF_B1 + n * BSTR1 + c2 * 2)         = hi;
        *(uint32_t*)(smem + OFF_B1 + n * BSTR1 + (112 + c2) * 2) = lo;
    }
    for (int i = tid; i < 64 * 40; i += THREADS) {        // W2: 40 k-pairs/row
        int n = i / 40, c2 = (i - n * 40) * 2;
        float w0 = W2[n * 80 + c2], w1 = W2[n * 80 + c2 + 1];
        uint32_t hi, lo; split_pack(w0, w1, hi, lo);
        *(uint32_t*)(smem + OFF_B2 + n * BSTR2 + c2 * 2)        = hi;
        *(uint32_t*)(smem + OFF_B2 + n * BSTR2 + (80 + c2) * 2) = lo;
    }
    if (tid < 80) b1s[tid] = b1[tid];
    if (tid < 64) b2s[tid] = b2[tid];
    __syncthreads();

    const int mrow  = (warp >> 1) * 16;   // 12 row-groups of 16
    const int ncolA = (warp & 1) * 40;    // 2 col-groups: phase A n40
    const int ncolB = (warp & 1) * 32;    // phase B n32
    const int rA = (lane >> 2);           // frag row within m16; second row rA+8
    const int cc = 2 * (lane & 3);        // frag col pair base within n8

    // ldmatrix lane-address components
    const int aRow  = lane & 15;          // A rows (x4): mrow..mrow+15
    const int aKof  = (lane >> 4) * 8;    // A k offset 0/8
    const int bRow4 = lane & 15;          // B rows (x4): nb..nb+15
    const int bKof4 = (lane >> 4) * 8;    // B k offset 0/8
    const int bRow2 = lane & 7;           // B rows (x2)
    const int bKof2 = ((lane >> 3) & 1) * 8;

    const int ntiles = (E + TILE - 1) / TILE;

    for (int tile = blockIdx.x; tile < ntiles; tile += gridDim.x) {
        const int e0 = tile * TILE;
        int rem = E - e0; if (rem > TILE) rem = TILE;

        // ---- stage A1: gather + split; f4 chunk covers k0..k0+3 ----
        for (int i = tid; i < TILE * 25; i += THREADS) {
            int r = i / 25;
            if (r >= rem) continue;
            int k0 = (i - r * 25) * 4;    // 0..96
            size_t ge = (size_t)(e0 + r);
            float4 x;
            if      (k0 < 16) x = *(const float4*)(dstf + ge * 16 + k0);
            else if (k0 < 48) x = *(const float4*)(dsth + ge * 32 + (k0 - 16));
            else if (k0 < 64) x = *(const float4*)(srcf + ge * 16 + (k0 - 48));
            else if (k0 < 96) x = *(const float4*)(srch + ge * 32 + (k0 - 64));
            else              x = make_float4(ef[ge], 0.0f, 0.0f, 0.0f);
            uint32_t h0, l0, h1, l1;
            split_pack(x.x, x.y, h0, l0);
            split_pack(x.z, x.w, h1, l1);
            char* rp = smem + OFF_A1 + r * ASTR1;
            *(uint32_t*)(rp + k0 * 2)             = h0;
            *(uint32_t*)(rp + k0 * 2 + 4)         = h1;
            *(uint32_t*)(rp + (112 + k0) * 2)     = l0;
            *(uint32_t*)(rp + (112 + k0) * 2 + 4) = l1;
        }
        __syncthreads();   // A1 visible; also orders prev-tile MMA B before epi-A writes below

        // ---- phase A: H[192x80], 3-term split, 21 k-steps ----
        float acc[5][4];
        #pragma unroll
        for (int j = 0; j < 5; j++)
            #pragma unroll
            for (int q = 0; q < 4; q++) acc[j][q] = 0.0f;

        {
            const uint32_t aBase  = sb + OFF_A1 + (mrow + aRow) * ASTR1 + aKof * 2;
            const uint32_t bBase0 = sb + OFF_B1 + (ncolA + bRow4)      * BSTR1 + bKof4 * 2;
            const uint32_t bBase1 = sb + OFF_B1 + (ncolA + 16 + bRow4) * BSTR1 + bKof4 * 2;
            const uint32_t bBase2 = sb + OFF_B1 + (ncolA + 32 + bRow2) * BSTR1 + bKof2 * 2;

            #pragma unroll
            for (int s = 0; s < 21; s++) {
                const int t  = (s < 7) ? 0 : ((s < 14) ? 1 : 2);
                const int sk = s - ((t == 1) ? 7 : ((t == 2) ? 14 : 0));
                const int kA = (((t == 1) ? 112 : 0) + sk * 16) * 2;
                const int kB = (((t == 2) ? 112 : 0) + sk * 16) * 2;
                uint32_t a0, a1, a2, a3, q0, q1, q2, q3;
                ldsm_x4(a0, a1, a2, a3, aBase + kA);
                ldsm_x4(q0, q1, q2, q3, bBase0 + kB);     // n-pair 0: j=0 (q0,q2), j=1 (q1,q3)
                mma16816(acc[0], a0, a1, a2, a3, q0, q2);
                mma16816(acc[1], a0, a1, a2, a3, q1, q3);
                ldsm_x4(q0, q1, q2, q3, bBase1 + kB);     // n-pair 1: j=2, j=3
                mma16816(acc[2], a0, a1, a2, a3, q0, q2);
                mma16816(acc[3], a0, a1, a2, a3, q1, q3);
                ldsm_x2(q0, q1, bBase2 + kB);             // j=4
                mma16816(acc[4], a0, a1, a2, a3, q0, q1);
            }
        }

        // ---- epilogue A: relu(+b1), split -> A2 (no barrier needed before:
        //      prev-tile A2 readers all precede the post-staging barrier) ----
        #pragma unroll
        for (int j = 0; j < 5; j++) {
            const int c0 = ncolA + 8 * j + cc;
            const float bb0 = b1s[c0], bb1 = b1s[c0 + 1];
            float h00 = fmaxf(acc[j][0] + bb0, 0.0f), h01 = fmaxf(acc[j][1] + bb1, 0.0f);
            float h10 = fmaxf(acc[j][2] + bb0, 0.0f), h11 = fmaxf(acc[j][3] + bb1, 0.0f);
            uint32_t hi, lo;
            char* rp0 = smem + OFF_A2 + (mrow + rA) * ASTR2;
            char* rp1 = smem + OFF_A2 + (mrow + rA + 8) * ASTR2;
            split_pack(h00, h01, hi, lo);
            *(uint32_t*)(rp0 + c0 * 2) = hi;  *(uint32_t*)(rp0 + (80 + c0) * 2) = lo;
            split_pack(h10, h11, hi, lo);
            *(uint32_t*)(rp1 + c0 * 2) = hi;  *(uint32_t*)(rp1 + (80 + c0) * 2) = lo;
        }
        __syncthreads();   // A2 complete before phase B reads

        // ---- phase B: O[192x64], 15 k-steps ----
        float acc2[4][4];
        #pragma unroll
        for (int j = 0; j < 4; j++)
            #pragma unroll
            for (int q = 0; q < 4; q++) acc2[j][q] = 0.0f;

        {
            const uint32_t aBase  = sb + OFF_A2 + (mrow + aRow) * ASTR2 + aKof * 2;
            const uint32_t bBase0 = sb + OFF_B2 + (ncolB + bRow4)      * BSTR2 + bKof4 * 2;
            const uint32_t bBase1 = sb + OFF_B2 + (ncolB + 16 + bRow4) * BSTR2 + bKof4 * 2;

            #pragma unroll
            for (int s = 0; s < 15; s++) {
                const int t  = (s < 5) ? 0 : ((s < 10) ? 1 : 2);
                const int sk = s - ((t == 1) ? 5 : ((t == 2) ? 10 : 0));
                const int kA = (((t == 1) ? 80 : 0) + sk * 16) * 2;
                const int kB = (((t == 2) ? 80 : 0) + sk * 16) * 2;
                uint32_t a0, a1, a2, a3, q0, q1, q2, q3;
                ldsm_x4(a0, a1, a2, a3, aBase + kA);
                ldsm_x4(q0, q1, q2, q3, bBase0 + kB);
                mma16816(acc2[0], a0, a1, a2, a3, q0, q2);
                mma16816(acc2[1], a0, a1, a2, a3, q1, q3);
                ldsm_x4(q0, q1, q2, q3, bBase1 + kB);
                mma16816(acc2[2], a0, a1, a2, a3, q0, q2);
                mma16816(acc2[3], a0, a1, a2, a3, q1, q3);
            }
        }

        // ---- epilogue B: tanh(+b2) -> direct STG.64 ----
        {
            const int gr0 = e0 + mrow + rA;
            const int gr1 = gr0 + 8;
            #pragma unroll
            for (int j = 0; j < 4; j++) {
                const int c0 = ncolB + 8 * j + cc;
                const float bb0 = b2s[c0], bb1 = b2s[c0 + 1];
                if (gr0 < E) {
                    float2 v = make_float2(fast_tanh(acc2[j][0] + bb0),
                                           fast_tanh(acc2[j][1] + bb1));
                    *(float2*)(out + (size_t)gr0 * 64 + c0) = v;
                }
                if (gr1 < E) {
                    float2 v = make_float2(fast_tanh(acc2[j][2] + bb0),
                                           fast_tanh(acc2[j][3] + bb1));
                    *(float2*)(out + (size_t)gr1 * 64 + c0) = v;
                }
            }
        }
        // no trailing barrier: next-tile A1 staging races only prev MMA A readers,
        // all of which precede the next post-staging barrier in program order... 
        // (A1 last read in MMA A(t); every warp's staging STS(t+1) happens after
        //  its own MMA A(t); cross-warp A1 safety is provided by the post-staging
        //  __syncthreads() gating MMA A(t+1), and stale reads cannot occur because
        //  no warp reads A1 between its staging STS and that barrier.)
    }
}

extern "C" void kernel_launch(void* const* d_in, const int* in_sizes, int n_in,
                              void* d_out, int out_size) {
    const float* dstf = (const float*)d_in[0];
    const float* dsth = (const float*)d_in[1];
    const float* srcf = (const float*)d_in[2];
    const float* srch = (const float*)d_in[3];
    const float* ef   = (const float*)d_in[4];
    const float* W1   = (const float*)d_in[5];
    const float* b1   = (const float*)d_in[6];
    const float* W2   = (const float*)d_in[7];
    const float* b2   = (const float*)d_in[8];
    float* out = (float*)d_out;
    const int E = in_sizes[4];
    (void)n_in; (void)out_size;

    cudaFuncSetAttribute(edge_mlp_mma,
                         cudaFuncAttributeMaxDynamicSharedMemorySize, SMEM_TOTAL);
    int sms = 148;
    cudaDeviceGetAttribute(&sms, cudaDevAttrMultiProcessorCount, 0);

    edge_mlp_mma<<<sms, THREADS, SMEM_TOTAL>>>(
        dstf, dsth, srcf, srch, ef, W1, b1, W2, b2, out, E);
}

// round 9
// speedup vs baseline: 1.6781x; 1.6781x over previous
#include <cuda_runtime.h>
#include <cuda_bf16.h>
#include <cstdint>

#define THREADS 512
#define TILE    128

// bf16 tiles, row stride in BYTES (stride/4 mod 32 = 20 -> 8-row LDSM conflict-free)
#define ASTR1 464   // A1: 128 x [xhi(112) | xlo(112)]
#define BSTR1 464   // B1: 80  x [whi(112) | wlo(112)]
#define ASTR2 336   // A2: 128 x [hhi(80)  | hlo(80)]
#define BSTR2 336   // B2: 64  x [whi(80)  | wlo(80)]

#define OFF_A1  0         // 128*464 = 59392
#define OFF_A2  59392     // 128*336 = 43008 -> 102400
#define OFF_B1  102400    // 80*464  = 37120 -> 139520
#define OFF_B2  139520    // 64*336  = 21504 -> 161024
#define OFF_B1S 161024    // 80 f32
#define OFF_B2S 161344    // 64 f32
#define SMEM_TOTAL 161664

__device__ __forceinline__ uint32_t smem_u32(const void* p) {
    uint32_t a;
    asm("{ .reg .u64 t; cvta.to.shared.u64 t, %1; cvt.u32.u64 %0, t; }" : "=r"(a) : "l"(p));
    return a;
}

__device__ __forceinline__ void split_pack(float x0, float x1, uint32_t& hi, uint32_t& lo) {
    uint16_t h0 = __bfloat16_as_ushort(__float2bfloat16_rn(x0));
    uint16_t h1 = __bfloat16_as_ushort(__float2bfloat16_rn(x1));
    float f0 = __uint_as_float((uint32_t)h0 << 16);
    float f1 = __uint_as_float((uint32_t)h1 << 16);
    uint16_t l0 = __bfloat16_as_ushort(__float2bfloat16_rn(x0 - f0));
    uint16_t l1 = __bfloat16_as_ushort(__float2bfloat16_rn(x1 - f1));
    hi = (uint32_t)h0 | ((uint32_t)h1 << 16);
    lo = (uint32_t)l0 | ((uint32_t)l1 << 16);
}

__device__ __forceinline__ float fast_tanh(float x) {
    float e = __expf(2.0f * x);
    return 1.0f - __fdividef(2.0f, e + 1.0f);
}

__device__ __forceinline__ void ldsm_x4(uint32_t& r0, uint32_t& r1, uint32_t& r2, uint32_t& r3,
                                        uint32_t addr) {
    asm volatile("ldmatrix.sync.aligned.m8n8.x4.shared.b16 {%0,%1,%2,%3}, [%4];"
        : "=r"(r0), "=r"(r1), "=r"(r2), "=r"(r3) : "r"(addr));
}
__device__ __forceinline__ void ldsm_x2(uint32_t& r0, uint32_t& r1, uint32_t addr) {
    asm volatile("ldmatrix.sync.aligned.m8n8.x2.shared.b16 {%0,%1}, [%2];"
        : "=r"(r0), "=r"(r1) : "r"(addr));
}

__device__ __forceinline__ void mma16816(float* d, uint32_t a0, uint32_t a1, uint32_t a2,
                                         uint32_t a3, uint32_t b0, uint32_t b1) {
    asm volatile(
        "mma.sync.aligned.m16n8k16.row.col.f32.bf16.bf16.f32 "
        "{%0,%1,%2,%3}, {%4,%5,%6,%7}, {%8,%9}, {%0,%1,%2,%3};"
        : "+f"(d[0]), "+f"(d[1]), "+f"(d[2]), "+f"(d[3])
        : "r"(a0), "r"(a1), "r"(a2), "r"(a3), "r"(b0), "r"(b1));
}

extern __shared__ char smem[];

__global__ void __launch_bounds__(THREADS, 1)
edge_mlp_mma(const float* __restrict__ dstf, const float* __restrict__ dsth,
             const float* __restrict__ srcf, const float* __restrict__ srch,
             const float* __restrict__ ef,
             const float* __restrict__ W1, const float* __restrict__ b1,
             const float* __restrict__ W2, const float* __restrict__ b2,
             float* __restrict__ out, int E)
{
    const uint32_t sb = smem_u32(smem);
    const int tid  = threadIdx.x;
    const int lane = tid & 31;
    const int warp = tid >> 5;            // 0..15
    float* b1s = (float*)(smem + OFF_B1S);
    float* b2s = (float*)(smem + OFF_B2S);

    // ---- one-time zero (covers all k-pads) ----
    for (int i = tid; i < OFF_B1S / 4; i += THREADS) ((uint32_t*)smem)[i] = 0u;
    __syncthreads();

    // ---- stage split weights ----
    for (int i = tid; i < 80 * 56; i += THREADS) {
        int n = i / 56, c2 = (i - n * 56) * 2;
        float w0 = (c2     < 97) ? W1[n * 97 + c2]     : 0.0f;
        float w1 = (c2 + 1 < 97) ? W1[n * 97 + c2 + 1] : 0.0f;
        uint32_t hi, lo; split_pack(w0, w1, hi, lo);
        *(uint32_t*)(smem + OFF_B1 + n * BSTR1 + c2 * 2)         = hi;
        *(uint32_t*)(smem + OFF_B1 + n * BSTR1 + (112 + c2) * 2) = lo;
    }
    for (int i = tid; i < 64 * 40; i += THREADS) {
        int n = i / 40, c2 = (i - n * 40) * 2;
        float w0 = W2[n * 80 + c2], w1 = W2[n * 80 + c2 + 1];
        uint32_t hi, lo; split_pack(w0, w1, hi, lo);
        *(uint32_t*)(smem + OFF_B2 + n * BSTR2 + c2 * 2)        = hi;
        *(uint32_t*)(smem + OFF_B2 + n * BSTR2 + (80 + c2) * 2) = lo;
    }
    if (tid < 80) b1s[tid] = b1[tid];
    if (tid < 64) b2s[tid] = b2[tid];
    __syncthreads();

    const int mrow  = (warp & 7) * 16;    // 8 row-groups of 16
    const int ncolA = (warp >> 3) * 40;   // phase A n40 col group
    const int ncolB = (warp >> 3) * 32;   // phase B n32 col group
    const int rA = (lane >> 2);           // frag row within m16
    const int cc = 2 * (lane & 3);        // frag col pair base within n8

    const int aRow  = lane & 15;
    const int aKof  = (lane >> 4) * 8;
    const int bRow4 = lane & 15;
    const int bKof4 = (lane >> 4) * 8;
    const int bRow2 = lane & 7;
    const int bKof2 = ((lane >> 3) & 1) * 8;

    // staging assignment: row = tid/4, chunks c = 4q + sub (q=0..5), + c=24 for sub==3
    const int srow = tid >> 2;
    const int sub  = tid & 3;

    const int ntiles = (E + TILE - 1) / TILE;

    // ---- prefetch first tile into registers ----
    float4 px[7];
    {
        int tile0 = blockIdx.x;
        if (tile0 < ntiles) {
            size_t ge = (size_t)(tile0 * TILE + srow);
            bool ok = (int)(ge) < E;
            #pragma unroll
            for (int q = 0; q < 6; q++) {
                int k0 = (4 * q + sub) * 4;
                float4 x = make_float4(0.f, 0.f, 0.f, 0.f);
                if (ok) {
                    if      (k0 < 16) x = *(const float4*)(dstf + ge * 16 + k0);
                    else if (k0 < 48) x = *(const float4*)(dsth + ge * 32 + (k0 - 16));
                    else if (k0 < 64) x = *(const float4*)(srcf + ge * 16 + (k0 - 48));
                    else              x = *(const float4*)(srch + ge * 32 + (k0 - 64));
                }
                px[q] = x;
            }
            px[6] = make_float4((sub == 3 && ok) ? ef[ge] : 0.0f, 0.f, 0.f, 0.f);
        }
    }

    for (int tile = blockIdx.x; tile < ntiles; tile += gridDim.x) {
        const int e0 = tile * TILE;

        // ---- STS prefetched tile -> A1 (split hi/lo) ----
        {
            char* rp = smem + OFF_A1 + srow * ASTR1;
            #pragma unroll
            for (int q = 0; q < 6; q++) {
                int k0 = (4 * q + sub) * 4;
                uint32_t h0, l0, h1, l1;
                split_pack(px[q].x, px[q].y, h0, l0);
                split_pack(px[q].z, px[q].w, h1, l1);
                *(uint32_t*)(rp + k0 * 2)             = h0;
                *(uint32_t*)(rp + k0 * 2 + 4)         = h1;
                *(uint32_t*)(rp + (112 + k0) * 2)     = l0;
                *(uint32_t*)(rp + (112 + k0) * 2 + 4) = l1;
            }
            if (sub == 3) {
                uint32_t h0, l0, h1, l1;
                split_pack(px[6].x, px[6].y, h0, l0);
                split_pack(px[6].z, px[6].w, h1, l1);
                *(uint32_t*)(rp + 96 * 2)             = h0;
                *(uint32_t*)(rp + 96 * 2 + 4)         = h1;
                *(uint32_t*)(rp + (112 + 96) * 2)     = l0;
                *(uint32_t*)(rp + (112 + 96) * 2 + 4) = l1;
            }
        }
        __syncthreads();   // bar1: A1 visible to all; gates mmaA

        // ---- prefetch NEXT tile (latency hidden behind mmaA/epiA/mmaB) ----
        {
            int nt = tile + gridDim.x;
            if (nt < ntiles) {
                size_t ge = (size_t)(nt * TILE + srow);
                bool ok = (int)(ge) < E;
                #pragma unroll
                for (int q = 0; q < 6; q++) {
                    int k0 = (4 * q + sub) * 4;
                    float4 x = make_float4(0.f, 0.f, 0.f, 0.f);
                    if (ok) {
                        if      (k0 < 16) x = *(const float4*)(dstf + ge * 16 + k0);
                        else if (k0 < 48) x = *(const float4*)(dsth + ge * 32 + (k0 - 16));
                        else if (k0 < 64) x = *(const float4*)(srcf + ge * 16 + (k0 - 48));
                        else              x = *(const float4*)(srch + ge * 32 + (k0 - 64));
                    }
                    px[q] = x;
                }
                px[6] = make_float4((sub == 3 && ok) ? ef[ge] : 0.0f, 0.f, 0.f, 0.f);
            }
        }

        // ---- phase A: H[128x80], 3-term split, 21 k-steps ----
        float acc[5][4];
        #pragma unroll
        for (int j = 0; j < 5; j++)
            #pragma unroll
            for (int q = 0; q < 4; q++) acc[j][q] = 0.0f;

        {
            const uint32_t aBase  = sb + OFF_A1 + (mrow + aRow) * ASTR1 + aKof * 2;
            const uint32_t bBase0 = sb + OFF_B1 + (ncolA + bRow4)      * BSTR1 + bKof4 * 2;
            const uint32_t bBase1 = sb + OFF_B1 + (ncolA + 16 + bRow4) * BSTR1 + bKof4 * 2;
            const uint32_t bBase2 = sb + OFF_B1 + (ncolA + 32 + bRow2) * BSTR1 + bKof2 * 2;

            #pragma unroll
            for (int s = 0; s < 21; s++) {
                const int t  = (s < 7) ? 0 : ((s < 14) ? 1 : 2);
                const int sk = s - ((t == 1) ? 7 : ((t == 2) ? 14 : 0));
                const int kA = (((t == 1) ? 112 : 0) + sk * 16) * 2;
                const int kB = (((t == 2) ? 112 : 0) + sk * 16) * 2;
                uint32_t a0, a1, a2, a3, q0, q1, q2, q3;
                ldsm_x4(a0, a1, a2, a3, aBase + kA);
                ldsm_x4(q0, q1, q2, q3, bBase0 + kB);
                mma16816(acc[0], a0, a1, a2, a3, q0, q2);
                mma16816(acc[1], a0, a1, a2, a3, q1, q3);
                ldsm_x4(q0, q1, q2, q3, bBase1 + kB);
                mma16816(acc[2], a0, a1, a2, a3, q0, q2);
                mma16816(acc[3], a0, a1, a2, a3, q1, q3);
                ldsm_x2(q0, q1, bBase2 + kB);
                mma16816(acc[4], a0, a1, a2, a3, q0, q1);
            }
        }

        // ---- epilogue A: relu(+b1), split -> A2 ----
        #pragma unroll
        for (int j = 0; j < 5; j++) {
            const int c0 = ncolA + 8 * j + cc;
            const float bb0 = b1s[c0], bb1 = b1s[c0 + 1];
            float h00 = fmaxf(acc[j][0] + bb0, 0.0f), h01 = fmaxf(acc[j][1] + bb1, 0.0f);
            float h10 = fmaxf(acc[j][2] + bb0, 0.0f), h11 = fmaxf(acc[j][3] + bb1, 0.0f);
            uint32_t hi, lo;
            char* rp0 = smem + OFF_A2 + (mrow + rA) * ASTR2;
            char* rp1 = smem + OFF_A2 + (mrow + rA + 8) * ASTR2;
            split_pack(h00, h01, hi, lo);
            *(uint32_t*)(rp0 + c0 * 2) = hi;  *(uint32_t*)(rp0 + (80 + c0) * 2) = lo;
            split_pack(h10, h11, hi, lo);
            *(uint32_t*)(rp1 + c0 * 2) = hi;  *(uint32_t*)(rp1 + (80 + c0) * 2) = lo;
        }
        __syncthreads();   // bar2: A2 complete; also proves all mmaA A1-reads done

        // ---- phase B: O[128x64], 15 k-steps ----
        float acc2[4][4];
        #pragma unroll
        for (int j = 0; j < 4; j++)
            #pragma unroll
            for (int q = 0; q < 4; q++) acc2[j][q] = 0.0f;

        {
            const uint32_t aBase  = sb + OFF_A2 + (mrow + aRow) * ASTR2 + aKof * 2;
            const uint32_t bBase0 = sb + OFF_B2 + (ncolB + bRow4)      * BSTR2 + bKof4 * 2;
            const uint32_t bBase1 = sb + OFF_B2 + (ncolB + 16 + bRow4) * BSTR2 + bKof4 * 2;

            #pragma unroll
            for (int s = 0; s < 15; s++) {
                const int t  = (s < 5) ? 0 : ((s < 10) ? 1 : 2);
                const int sk = s - ((t == 1) ? 5 : ((t == 2) ? 10 : 0));
                const int kA = (((t == 1) ? 80 : 0) + sk * 16) * 2;
                const int kB = (((t == 2) ? 80 : 0) + sk * 16) * 2;
                uint32_t a0, a1, a2, a3, q0, q1, q2, q3;
                ldsm_x4(a0, a1, a2, a3, aBase + kA);
                ldsm_x4(q0, q1, q2, q3, bBase0 + kB);
                mma16816(acc2[0], a0, a1, a2, a3, q0, q2);
                mma16816(acc2[1], a0, a1, a2, a3, q1, q3);
                ldsm_x4(q0, q1, q2, q3, bBase1 + kB);
                mma16816(acc2[2], a0, a1, a2, a3, q0, q2);
                mma16816(acc2[3], a0, a1, a2, a3, q1, q3);
            }
        }

        // ---- epilogue B: tanh(+b2) -> direct STG.64 ----
        {
            const int gr0 = e0 + mrow + rA;
            const int gr1 = gr0 + 8;
            #pragma unroll
            for (int j = 0; j < 4; j++) {
                const int c0 = ncolB + 8 * j + cc;
                const float bb0 = b2s[c0], bb1 = b2s[c0 + 1];
                if (gr0 < E) {
                    float2 v = make_float2(fast_tanh(acc2[j][0] + bb0),
                                           fast_tanh(acc2[j][1] + bb1));
                    *(float2*)(out + (size_t)gr0 * 64 + c0) = v;
                }
                if (gr1 < E) {
                    float2 v = make_float2(fast_tanh(acc2[j][2] + bb0),
                                           fast_tanh(acc2[j][3] + bb1));
                    *(float2*)(out + (size_t)gr1 * 64 + c0) = v;
                }
            }
        }
        // next iteration's STS(t+1) is safe: bar2 proved all mmaA(t) reads of A1
        // completed; mmaB(t) reads only A2/B2, disjoint from A1.
    }
}

extern "C" void kernel_launch(void* const* d_in, const int* in_sizes, int n_in,
                              void* d_out, int out_size) {
    const float* dstf = (const float*)d_in[0];
    const float* dsth = (const float*)d_in[1];
    const float* srcf = (const float*)d_in[2];
    const float* srch = (const float*)d_in[3];
    const float* ef   = (const float*)d_in[4];
    const float* W1   = (const float*)d_in[5];
    const float* b1   = (const float*)d_in[6];
    const float* W2   = (const float*)d_in[7];
    const float* b2   = (const float*)d_in[8];
    float* out = (float*)d_out;
    const int E = in_sizes[4];
    (void)n_in; (void)out_size;

    cudaFuncSetAttribute(edge_mlp_mma,
                         cudaFuncAttributeMaxDynamicSharedMemorySize, SMEM_TOTAL);
    int sms = 148;
    cudaDeviceGetAttribute(&sms, cudaDevAttrMultiProcessorCount, 0);

    edge_mlp_mma<<<sms, THREADS, SMEM_TOTAL>>>(
        dstf, dsth, srcf, srch, ef, W1, b1, W2, b2, out, E);
}

// round 10
// speedup vs baseline: 1.7021x; 1.0143x over previous
#include <cuda_runtime.h>
#include <cuda_bf16.h>
#include <cstdint>

#define THREADS 256
#define TILE    64

// bf16 tiles, row stride in BYTES (stride/4 mod 32 = 20 -> 8-row LDSM conflict-free)
#define ASTR1 464   // A1: 64 x [xhi(112) | xlo(112)]
#define BSTR1 464   // B1: 80 x [whi(112) | wlo(112)]
#define ASTR2 336   // A2: 64 x [hhi(80)  | hlo(80)]
#define BSTR2 336   // B2: 64 x [whi(80)  | wlo(80)]

#define OFF_A1  0         // 64*464 = 29696
#define OFF_A2  29696     // 64*336 = 21504 -> 51200
#define OFF_B1  51200     // 80*464 = 37120 -> 88320
#define OFF_B2  88320     // 64*336 = 21504 -> 109824
#define OFF_B1S 109824    // 80 f32
#define OFF_B2S 110144    // 64 f32
#define SMEM_TOTAL 110400 // x2 CTAs = 220800 <= 228KB/SM

__device__ __forceinline__ uint32_t smem_u32(const void* p) {
    uint32_t a;
    asm("{ .reg .u64 t; cvta.to.shared.u64 t, %1; cvt.u32.u64 %0, t; }" : "=r"(a) : "l"(p));
    return a;
}

__device__ __forceinline__ void split_pack(float x0, float x1, uint32_t& hi, uint32_t& lo) {
    uint16_t h0 = __bfloat16_as_ushort(__float2bfloat16_rn(x0));
    uint16_t h1 = __bfloat16_as_ushort(__float2bfloat16_rn(x1));
    float f0 = __uint_as_float((uint32_t)h0 << 16);
    float f1 = __uint_as_float((uint32_t)h1 << 16);
    uint16_t l0 = __bfloat16_as_ushort(__float2bfloat16_rn(x0 - f0));
    uint16_t l1 = __bfloat16_as_ushort(__float2bfloat16_rn(x1 - f1));
    hi = (uint32_t)h0 | ((uint32_t)h1 << 16);
    lo = (uint32_t)l0 | ((uint32_t)l1 << 16);
}

__device__ __forceinline__ float fast_tanh(float x) {
    float e = __expf(2.0f * x);
    return 1.0f - __fdividef(2.0f, e + 1.0f);
}

__device__ __forceinline__ void ldsm_x4(uint32_t& r0, uint32_t& r1, uint32_t& r2, uint32_t& r3,
                                        uint32_t addr) {
    asm volatile("ldmatrix.sync.aligned.m8n8.x4.shared.b16 {%0,%1,%2,%3}, [%4];"
        : "=r"(r0), "=r"(r1), "=r"(r2), "=r"(r3) : "r"(addr));
}
__device__ __forceinline__ void ldsm_x2(uint32_t& r0, uint32_t& r1, uint32_t addr) {
    asm volatile("ldmatrix.sync.aligned.m8n8.x2.shared.b16 {%0,%1}, [%2];"
        : "=r"(r0), "=r"(r1) : "r"(addr));
}

__device__ __forceinline__ void mma16816(float* d, uint32_t a0, uint32_t a1, uint32_t a2,
                                         uint32_t a3, uint32_t b0, uint32_t b1) {
    asm volatile(
        "mma.sync.aligned.m16n8k16.row.col.f32.bf16.bf16.f32 "
        "{%0,%1,%2,%3}, {%4,%5,%6,%7}, {%8,%9}, {%0,%1,%2,%3};"
        : "+f"(d[0]), "+f"(d[1]), "+f"(d[2]), "+f"(d[3])
        : "r"(a0), "r"(a1), "r"(a2), "r"(a3), "r"(b0), "r"(b1));
}

extern __shared__ char smem[];

__global__ void __launch_bounds__(THREADS, 2)
edge_mlp_mma(const float* __restrict__ dstf, const float* __restrict__ dsth,
             const float* __restrict__ srcf, const float* __restrict__ srch,
             const float* __restrict__ ef,
             const float* __restrict__ W1, const float* __restrict__ b1,
             const float* __restrict__ W2, const float* __restrict__ b2,
             float* __restrict__ out, int E)
{
    const uint32_t sb = smem_u32(smem);
    const int tid  = threadIdx.x;
    const int lane = tid & 31;
    const int warp = tid >> 5;            // 0..7
    float* b1s = (float*)(smem + OFF_B1S);
    float* b2s = (float*)(smem + OFF_B2S);

    // ---- one-time zero (covers all k-pads) ----
    for (int i = tid; i < OFF_B1S / 4; i += THREADS) ((uint32_t*)smem)[i] = 0u;
    __syncthreads();

    // ---- stage split weights (per CTA) ----
    for (int i = tid; i < 80 * 56; i += THREADS) {
        int n = i / 56, c2 = (i - n * 56) * 2;
        float w0 = (c2     < 97) ? W1[n * 97 + c2]     : 0.0f;
        float w1 = (c2 + 1 < 97) ? W1[n * 97 + c2 + 1] : 0.0f;
        uint32_t hi, lo; split_pack(w0, w1, hi, lo);
        *(uint32_t*)(smem + OFF_B1 + n * BSTR1 + c2 * 2)         = hi;
        *(uint32_t*)(smem + OFF_B1 + n * BSTR1 + (112 + c2) * 2) = lo;
    }
    for (int i = tid; i < 64 * 40; i += THREADS) {
        int n = i / 40, c2 = (i - n * 40) * 2;
        float w0 = W2[n * 80 + c2], w1 = W2[n * 80 + c2 + 1];
        uint32_t hi, lo; split_pack(w0, w1, hi, lo);
        *(uint32_t*)(smem + OFF_B2 + n * BSTR2 + c2 * 2)        = hi;
        *(uint32_t*)(smem + OFF_B2 + n * BSTR2 + (80 + c2) * 2) = lo;
    }
    if (tid < 80) b1s[tid] = b1[tid];
    if (tid < 64) b2s[tid] = b2[tid];
    __syncthreads();

    const int mrow  = (warp & 3) * 16;    // 4 row-groups of 16
    const int ncolA = (warp >> 2) * 40;   // phase A n40 col group
    const int ncolB = (warp >> 2) * 32;   // phase B n32 col group
    const int rA = (lane >> 2);
    const int cc = 2 * (lane & 3);

    const int aRow  = lane & 15;
    const int aKof  = (lane >> 4) * 8;
    const int bRow4 = lane & 15;
    const int bKof4 = (lane >> 4) * 8;
    const int bRow2 = lane & 7;
    const int bKof2 = ((lane >> 3) & 1) * 8;

    // staging: row = tid/4 (0..63), chunks c = 4q + sub
    const int srow = tid >> 2;
    const int sub  = tid & 3;

    const int ntiles = (E + TILE - 1) / TILE;

    // ---- prefetch first tile into registers ----
    float4 px[7];
    {
        int tile0 = blockIdx.x;
        if (tile0 < ntiles) {
            size_t ge = (size_t)(tile0 * TILE + srow);
            bool ok = (int)(ge) < E;
            #pragma unroll
            for (int q = 0; q < 6; q++) {
                int k0 = (4 * q + sub) * 4;
                float4 x = make_float4(0.f, 0.f, 0.f, 0.f);
                if (ok) {
                    if      (k0 < 16) x = *(const float4*)(dstf + ge * 16 + k0);
                    else if (k0 < 48) x = *(const float4*)(dsth + ge * 32 + (k0 - 16));
                    else if (k0 < 64) x = *(const float4*)(srcf + ge * 16 + (k0 - 48));
                    else              x = *(const float4*)(srch + ge * 32 + (k0 - 64));
                }
                px[q] = x;
            }
            px[6] = make_float4((sub == 3 && ok) ? ef[ge] : 0.0f, 0.f, 0.f, 0.f);
        }
    }

    for (int tile = blockIdx.x; tile < ntiles; tile += gridDim.x) {
        const int e0 = tile * TILE;

        // ---- STS prefetched tile -> A1 (split hi/lo) ----
        {
            char* rp = smem + OFF_A1 + srow * ASTR1;
            #pragma unroll
            for (int q = 0; q < 6; q++) {
                int k0 = (4 * q + sub) * 4;
                uint32_t h0, l0, h1, l1;
                split_pack(px[q].x, px[q].y, h0, l0);
                split_pack(px[q].z, px[q].w, h1, l1);
                *(uint32_t*)(rp + k0 * 2)             = h0;
                *(uint32_t*)(rp + k0 * 2 + 4)         = h1;
                *(uint32_t*)(rp + (112 + k0) * 2)     = l0;
                *(uint32_t*)(rp + (112 + k0) * 2 + 4) = l1;
            }
            if (sub == 3) {
                uint32_t h0, l0, h1, l1;
                split_pack(px[6].x, px[6].y, h0, l0);
                split_pack(px[6].z, px[6].w, h1, l1);
                *(uint32_t*)(rp + 96 * 2)             = h0;
                *(uint32_t*)(rp + 96 * 2 + 4)         = h1;
                *(uint32_t*)(rp + (112 + 96) * 2)     = l0;
                *(uint32_t*)(rp + (112 + 96) * 2 + 4) = l1;
            }
        }
        __syncthreads();   // bar1: A1 visible; gates mmaA

        // ---- prefetch NEXT tile (latency hidden behind mmaA/epiA/mmaB) ----
        {
            int nt = tile + gridDim.x;
            if (nt < ntiles) {
                size_t ge = (size_t)(nt * TILE + srow);
                bool ok = (int)(ge) < E;
                #pragma unroll
                for (int q = 0; q < 6; q++) {
                    int k0 = (4 * q + sub) * 4;
                    float4 x = make_float4(0.f, 0.f, 0.f, 0.f);
                    if (ok) {
                        if      (k0 < 16) x = *(const float4*)(dstf + ge * 16 + k0);
                        else if (k0 < 48) x = *(const float4*)(dsth + ge * 32 + (k0 - 16));
                        else if (k0 < 64) x = *(const float4*)(srcf + ge * 16 + (k0 - 48));
                        else              x = *(const float4*)(srch + ge * 32 + (k0 - 64));
                    }
                    px[q] = x;
                }
                px[6] = make_float4((sub == 3 && ok) ? ef[ge] : 0.0f, 0.f, 0.f, 0.f);
            }
        }

        // ---- phase A: H[64x80], 3-term split, 21 k-steps ----
        float acc[5][4];
        #pragma unroll
        for (int j = 0; j < 5; j++)
            #pragma unroll
            for (int q = 0; q < 4; q++) acc[j][q] = 0.0f;

        {
            const uint32_t aBase  = sb + OFF_A1 + (mrow + aRow) * ASTR1 + aKof * 2;
            const uint32_t bBase0 = sb + OFF_B1 + (ncolA + bRow4)      * BSTR1 + bKof4 * 2;
            const uint32_t bBase1 = sb + OFF_B1 + (ncolA + 16 + bRow4) * BSTR1 + bKof4 * 2;
            const uint32_t bBase2 = sb + OFF_B1 + (ncolA + 32 + bRow2) * BSTR1 + bKof2 * 2;

            #pragma unroll
            for (int s = 0; s < 21; s++) {
                const int t  = (s < 7) ? 0 : ((s < 14) ? 1 : 2);
                const int sk = s - ((t == 1) ? 7 : ((t == 2) ? 14 : 0));
                const int kA = (((t == 1) ? 112 : 0) + sk * 16) * 2;
                const int kB = (((t == 2) ? 112 : 0) + sk * 16) * 2;
                uint32_t a0, a1, a2, a3, q0, q1, q2, q3;
                ldsm_x4(a0, a1, a2, a3, aBase + kA);
                ldsm_x4(q0, q1, q2, q3, bBase0 + kB);
                mma16816(acc[0], a0, a1, a2, a3, q0, q2);
                mma16816(acc[1], a0, a1, a2, a3, q1, q3);
                ldsm_x4(q0, q1, q2, q3, bBase1 + kB);
                mma16816(acc[2], a0, a1, a2, a3, q0, q2);
                mma16816(acc[3], a0, a1, a2, a3, q1, q3);
                ldsm_x2(q0, q1, bBase2 + kB);
                mma16816(acc[4], a0, a1, a2, a3, q0, q1);
            }
        }

        // ---- epilogue A: relu(+b1), split -> A2 ----
        #pragma unroll
        for (int j = 0; j < 5; j++) {
            const int c0 = ncolA + 8 * j + cc;
            const float bb0 = b1s[c0], bb1 = b1s[c0 + 1];
            float h00 = fmaxf(acc[j][0] + bb0, 0.0f), h01 = fmaxf(acc[j][1] + bb1, 0.0f);
            float h10 = fmaxf(acc[j][2] + bb0, 0.0f), h11 = fmaxf(acc[j][3] + bb1, 0.0f);
            uint32_t hi, lo;
            char* rp0 = smem + OFF_A2 + (mrow + rA) * ASTR2;
            char* rp1 = smem + OFF_A2 + (mrow + rA + 8) * ASTR2;
            split_pack(h00, h01, hi, lo);
            *(uint32_t*)(rp0 + c0 * 2) = hi;  *(uint32_t*)(rp0 + (80 + c0) * 2) = lo;
            split_pack(h10, h11, hi, lo);
            *(uint32_t*)(rp1 + c0 * 2) = hi;  *(uint32_t*)(rp1 + (80 + c0) * 2) = lo;
        }
        __syncthreads();   // bar2: A2 complete; also proves all mmaA A1-reads done

        // ---- phase B: O[64x64], 15 k-steps ----
        float acc2[4][4];
        #pragma unroll
        for (int j = 0; j < 4; j++)
            #pragma unroll
            for (int q = 0; q < 4; q++) acc2[j][q] = 0.0f;

        {
            const uint32_t aBase  = sb + OFF_A2 + (mrow + aRow) * ASTR2 + aKof * 2;
            const uint32_t bBase0 = sb + OFF_B2 + (ncolB + bRow4)      * BSTR2 + bKof4 * 2;
            const uint32_t bBase1 = sb + OFF_B2 + (ncolB + 16 + bRow4) * BSTR2 + bKof4 * 2;

            #pragma unroll
            for (int s = 0; s < 15; s++) {
                const int t  = (s < 5) ? 0 : ((s < 10) ? 1 : 2);
                const int sk = s - ((t == 1) ? 5 : ((t == 2) ? 10 : 0));
                const int kA = (((t == 1) ? 80 : 0) + sk * 16) * 2;
                const int kB = (((t == 2) ? 80 : 0) + sk * 16) * 2;
                uint32_t a0, a1, a2, a3, q0, q1, q2, q3;
                ldsm_x4(a0, a1, a2, a3, aBase + kA);
                ldsm_x4(q0, q1, q2, q3, bBase0 + kB);
                mma16816(acc2[0], a0, a1, a2, a3, q0, q2);
                mma16816(acc2[1], a0, a1, a2, a3, q1, q3);
                ldsm_x4(q0, q1, q2, q3, bBase1 + kB);
                mma16816(acc2[2], a0, a1, a2, a3, q0, q2);
                mma16816(acc2[3], a0, a1, a2, a3, q1, q3);
            }
        }

        // ---- epilogue B: tanh(+b2) -> direct STG.64 ----
        {
            const int gr0 = e0 + mrow + rA;
            const int gr1 = gr0 + 8;
            #pragma unroll
            for (int j = 0; j < 4; j++) {
                const int c0 = ncolB + 8 * j + cc;
                const float bb0 = b2s[c0], bb1 = b2s[c0 + 1];
                if (gr0 < E) {
                    float2 v = make_float2(fast_tanh(acc2[j][0] + bb0),
                                           fast_tanh(acc2[j][1] + bb1));
                    *(float2*)(out + (size_t)gr0 * 64 + c0) = v;
                }
                if (gr1 < E) {
                    float2 v = make_float2(fast_tanh(acc2[j][2] + bb0),
                                           fast_tanh(acc2[j][3] + bb1));
                    *(float2*)(out + (size_t)gr1 * 64 + c0) = v;
                }
            }
        }
        // next iteration's STS(t+1) safe: bar2 proved all mmaA(t) A1-reads done.
    }
}

extern "C" void kernel_launch(void* const* d_in, const int* in_sizes, int n_in,
                              void* d_out, int out_size) {
    const float* dstf = (const float*)d_in[0];
    const float* dsth = (const float*)d_in[1];
    const float* srcf = (const float*)d_in[2];
    const float* srch = (const float*)d_in[3];
    const float* ef   = (const float*)d_in[4];
    const float* W1   = (const float*)d_in[5];
    const float* b1   = (const float*)d_in[6];
    const float* W2   = (const float*)d_in[7];
    const float* b2   = (const float*)d_in[8];
    float* out = (float*)d_out;
    const int E = in_sizes[4];
    (void)n_in; (void)out_size;

    cudaFuncSetAttribute(edge_mlp_mma,
                         cudaFuncAttributeMaxDynamicSharedMemorySize, SMEM_TOTAL);
    int sms = 148;
    cudaDeviceGetAttribute(&sms, cudaDevAttrMultiProcessorCount, 0);

    edge_mlp_mma<<<2 * sms, THREADS, SMEM_TOTAL>>>(
        dstf, dsth, srcf, srch, ef, W1, b1, W2, b2, out, E);
}

// round 11
// speedup vs baseline: 1.8780x; 1.1033x over previous
#include <cuda_runtime.h>
#include <cuda_bf16.h>
#include <cstdint>

#define THREADS 256
#define TILE    128

// bf16 tiles, row stride in BYTES (stride/16 odd -> 8-row LDSM phase conflict-free)
#define ASTR1 464   // A1: 128 x [xhi(112) | xlo(112)]
#define BSTR1 464   // B1: 80  x [whi(112) | wlo(112)]
#define ASTR2 336   // A2: 128 x [hhi(80)  | hlo(80)]
#define BSTR2 336   // B2: 64  x [whi(80)  | wlo(80)]

#define OFF_A1  0         // 128*464 = 59392
#define OFF_A2  59392     // 128*336 = 43008 -> 102400
#define OFF_B1  102400    // 80*464  = 37120 -> 139520
#define OFF_B2  139520    // 64*336  = 21504 -> 161024
#define OFF_B1S 161024    // 80 f32
#define OFF_B2S 161344    // 64 f32
#define SMEM_TOTAL 161664

__device__ __forceinline__ uint32_t smem_u32(const void* p) {
    uint32_t a;
    asm("{ .reg .u64 t; cvta.to.shared.u64 t, %1; cvt.u32.u64 %0, t; }" : "=r"(a) : "l"(p));
    return a;
}

__device__ __forceinline__ void split_pack(float x0, float x1, uint32_t& hi, uint32_t& lo) {
    uint16_t h0 = __bfloat16_as_ushort(__float2bfloat16_rn(x0));
    uint16_t h1 = __bfloat16_as_ushort(__float2bfloat16_rn(x1));
    float f0 = __uint_as_float((uint32_t)h0 << 16);
    float f1 = __uint_as_float((uint32_t)h1 << 16);
    uint16_t l0 = __bfloat16_as_ushort(__float2bfloat16_rn(x0 - f0));
    uint16_t l1 = __bfloat16_as_ushort(__float2bfloat16_rn(x1 - f1));
    hi = (uint32_t)h0 | ((uint32_t)h1 << 16);
    lo = (uint32_t)l0 | ((uint32_t)l1 << 16);
}

__device__ __forceinline__ float fast_tanh(float x) {
    float e = __expf(2.0f * x);
    return 1.0f - __fdividef(2.0f, e + 1.0f);
}

__device__ __forceinline__ void ldsm_x4(uint32_t& r0, uint32_t& r1, uint32_t& r2, uint32_t& r3,
                                        uint32_t addr) {
    asm volatile("ldmatrix.sync.aligned.m8n8.x4.shared.b16 {%0,%1,%2,%3}, [%4];"
        : "=r"(r0), "=r"(r1), "=r"(r2), "=r"(r3) : "r"(addr));
}
__device__ __forceinline__ void ldsm_x2(uint32_t& r0, uint32_t& r1, uint32_t addr) {
    asm volatile("ldmatrix.sync.aligned.m8n8.x2.shared.b16 {%0,%1}, [%2];"
        : "=r"(r0), "=r"(r1) : "r"(addr));
}

__device__ __forceinline__ void mma16816(float* d, uint32_t a0, uint32_t a1, uint32_t a2,
                                         uint32_t a3, uint32_t b0, uint32_t b1) {
    asm volatile(
        "mma.sync.aligned.m16n8k16.row.col.f32.bf16.bf16.f32 "
        "{%0,%1,%2,%3}, {%4,%5,%6,%7}, {%8,%9}, {%0,%1,%2,%3};"
        : "+f"(d[0]), "+f"(d[1]), "+f"(d[2]), "+f"(d[3])
        : "r"(a0), "r"(a1), "r"(a2), "r"(a3), "r"(b0), "r"(b1));
}

extern __shared__ char smem[];

__global__ void __launch_bounds__(THREADS, 1)
edge_mlp_mma(const float* __restrict__ dstf, const float* __restrict__ dsth,
             const float* __restrict__ srcf, const float* __restrict__ srch,
             const float* __restrict__ ef,
             const float* __restrict__ W1, const float* __restrict__ b1,
             const float* __restrict__ W2, const float* __restrict__ b2,
             float* __restrict__ out, int E)
{
    const uint32_t sb = smem_u32(smem);
    const int tid  = threadIdx.x;
    const int lane = tid & 31;
    const int warp = tid >> 5;            // 0..7
    float* b1s = (float*)(smem + OFF_B1S);
    float* b2s = (float*)(smem + OFF_B2S);

    // ---- one-time zero (covers all k-pads) ----
    for (int i = tid; i < OFF_B1S / 4; i += THREADS) ((uint32_t*)smem)[i] = 0u;
    __syncthreads();

    // ---- stage split weights ----
    for (int i = tid; i < 80 * 56; i += THREADS) {
        int n = i / 56, c2 = (i - n * 56) * 2;
        float w0 = (c2     < 97) ? W1[n * 97 + c2]     : 0.0f;
        float w1 = (c2 + 1 < 97) ? W1[n * 97 + c2 + 1] : 0.0f;
        uint32_t hi, lo; split_pack(w0, w1, hi, lo);
        *(uint32_t*)(smem + OFF_B1 + n * BSTR1 + c2 * 2)         = hi;
        *(uint32_t*)(smem + OFF_B1 + n * BSTR1 + (112 + c2) * 2) = lo;
    }
    for (int i = tid; i < 64 * 40; i += THREADS) {
        int n = i / 40, c2 = (i - n * 40) * 2;
        float w0 = W2[n * 80 + c2], w1 = W2[n * 80 + c2 + 1];
        uint32_t hi, lo; split_pack(w0, w1, hi, lo);
        *(uint32_t*)(smem + OFF_B2 + n * BSTR2 + c2 * 2)        = hi;
        *(uint32_t*)(smem + OFF_B2 + n * BSTR2 + (80 + c2) * 2) = lo;
    }
    if (tid < 80) b1s[tid] = b1[tid];
    if (tid < 64) b2s[tid] = b2[tid];
    __syncthreads();

    // warp tile: m32 x n40 (phase A) / m32 x n32 (phase B)
    const int mrow  = (warp & 3) * 32;    // 4 row-groups of 32
    const int ncolA = (warp >> 2) * 40;   // 2 n-groups
    const int ncolB = (warp >> 2) * 32;
    const int rA = (lane >> 2);           // frag row within m16 half
    const int cc = 2 * (lane & 3);

    const int aRow  = lane & 15;
    const int aKof  = (lane >> 4) * 8;
    const int bRow4 = lane & 15;
    const int bKof4 = (lane >> 4) * 8;
    const int bRow2 = lane & 7;
    const int bKof2 = ((lane >> 3) & 1) * 8;

    // staging: 2 threads per row; sub selects even/odd float4 chunks
    const int srow = tid >> 1;            // 0..127
    const int sub  = tid & 1;

    const int ntiles = (E + TILE - 1) / TILE;

    // ---- prefetch first tile into registers ----
    float4 px[12];
    float  pef;
    {
        int tile0 = blockIdx.x;
        if (tile0 < ntiles) {
            size_t ge = (size_t)(tile0 * TILE + srow);
            bool ok = (int)(ge) < E;
            #pragma unroll
            for (int q = 0; q < 12; q++) {
                int k0 = (2 * q + sub) * 4;
                float4 x = make_float4(0.f, 0.f, 0.f, 0.f);
                if (ok) {
                    if      (k0 < 16) x = *(const float4*)(dstf + ge * 16 + k0);
                    else if (k0 < 48) x = *(const float4*)(dsth + ge * 32 + (k0 - 16));
                    else if (k0 < 64) x = *(const float4*)(srcf + ge * 16 + (k0 - 48));
                    else              x = *(const float4*)(srch + ge * 32 + (k0 - 64));
                }
                px[q] = x;
            }
            pef = (sub == 0 && ok) ? ef[ge] : 0.0f;
        }
    }

    for (int tile = blockIdx.x; tile < ntiles; tile += gridDim.x) {
        const int e0 = tile * TILE;

        // ---- STS prefetched tile -> A1 (split hi/lo) ----
        {
            char* rp = smem + OFF_A1 + srow * ASTR1;
            #pragma unroll
            for (int q = 0; q < 12; q++) {
                int k0 = (2 * q + sub) * 4;
                uint32_t h0, l0, h1, l1;
                split_pack(px[q].x, px[q].y, h0, l0);
                split_pack(px[q].z, px[q].w, h1, l1);
                *(uint32_t*)(rp + k0 * 2)             = h0;
                *(uint32_t*)(rp + k0 * 2 + 4)         = h1;
                *(uint32_t*)(rp + (112 + k0) * 2)     = l0;
                *(uint32_t*)(rp + (112 + k0) * 2 + 4) = l1;
            }
            if (sub == 0) {   // ef at col 96; cols 97..99 stay zero from init
                uint32_t hi, lo; split_pack(pef, 0.0f, hi, lo);
                *(uint32_t*)(rp + 96 * 2)         = hi;
                *(uint32_t*)(rp + (112 + 96) * 2) = lo;
            }
        }
        __syncthreads();   // bar1: A1 visible; gates mmaA

        // ---- prefetch NEXT tile (latency hidden behind mmaA/epiA/mmaB) ----
        {
            int nt = tile + gridDim.x;
            if (nt < ntiles) {
                size_t ge = (size_t)(nt * TILE + srow);
                bool ok = (int)(ge) < E;
                #pragma unroll
                for (int q = 0; q < 12; q++) {
                    int k0 = (2 * q + sub) * 4;
                    float4 x = make_float4(0.f, 0.f, 0.f, 0.f);
                    if (ok) {
                        if      (k0 < 16) x = *(const float4*)(dstf + ge * 16 + k0);
                        else if (k0 < 48) x = *(const float4*)(dsth + ge * 32 + (k0 - 16));
                        else if (k0 < 64) x = *(const float4*)(srcf + ge * 16 + (k0 - 48));
                        else              x = *(const float4*)(srch + ge * 32 + (k0 - 64));
                    }
                    px[q] = x;
                }
                pef = (sub == 0 && ok) ? ef[ge] : 0.0f;
            }
        }

        // ---- phase A: H[128x80], warp m32xn40, 21 k-steps ----
        float acc[2][5][4];
        #pragma unroll
        for (int h = 0; h < 2; h++)
            #pragma unroll
            for (int j = 0; j < 5; j++)
                #pragma unroll
                for (int q = 0; q < 4; q++) acc[h][j][q] = 0.0f;

        {
            const uint32_t aBase0 = sb + OFF_A1 + (mrow + aRow) * ASTR1 + aKof * 2;
            const uint32_t aBase1 = aBase0 + 16 * ASTR1;
            const uint32_t bBase0 = sb + OFF_B1 + (ncolA + bRow4)      * BSTR1 + bKof4 * 2;
            const uint32_t bBase1 = sb + OFF_B1 + (ncolA + 16 + bRow4) * BSTR1 + bKof4 * 2;
            const uint32_t bBase2 = sb + OFF_B1 + (ncolA + 32 + bRow2) * BSTR1 + bKof2 * 2;

            #pragma unroll
            for (int s = 0; s < 21; s++) {
                const int t  = (s < 7) ? 0 : ((s < 14) ? 1 : 2);
                const int sk = s - ((t == 1) ? 7 : ((t == 2) ? 14 : 0));
                const int kA = (((t == 1) ? 112 : 0) + sk * 16) * 2;
                const int kB = (((t == 2) ? 112 : 0) + sk * 16) * 2;
                uint32_t a0, a1, a2, a3, c0, c1, c2, c3, q0, q1, q2, q3;
                ldsm_x4(a0, a1, a2, a3, aBase0 + kA);
                ldsm_x4(c0, c1, c2, c3, aBase1 + kA);
                ldsm_x4(q0, q1, q2, q3, bBase0 + kB);
                mma16816(acc[0][0], a0, a1, a2, a3, q0, q2);
                mma16816(acc[1][0], c0, c1, c2, c3, q0, q2);
                mma16816(acc[0][1], a0, a1, a2, a3, q1, q3);
                mma16816(acc[1][1], c0, c1, c2, c3, q1, q3);
                ldsm_x4(q0, q1, q2, q3, bBase1 + kB);
                mma16816(acc[0][2], a0, a1, a2, a3, q0, q2);
                mma16816(acc[1][2], c0, c1, c2, c3, q0, q2);
                mma16816(acc[0][3], a0, a1, a2, a3, q1, q3);
                mma16816(acc[1][3], c0, c1, c2, c3, q1, q3);
                ldsm_x2(q0, q1, bBase2 + kB);
                mma16816(acc[0][4], a0, a1, a2, a3, q0, q1);
                mma16816(acc[1][4], c0, c1, c2, c3, q0, q1);
            }
        }

        // ---- epilogue A: relu(+b1), split -> A2 ----
        #pragma unroll
        for (int h = 0; h < 2; h++) {
            #pragma unroll
            for (int j = 0; j < 5; j++) {
                const int c0 = ncolA + 8 * j + cc;
                const float bb0 = b1s[c0], bb1 = b1s[c0 + 1];
                float h00 = fmaxf(acc[h][j][0] + bb0, 0.0f);
                float h01 = fmaxf(acc[h][j][1] + bb1, 0.0f);
                float h10 = fmaxf(acc[h][j][2] + bb0, 0.0f);
                float h11 = fmaxf(acc[h][j][3] + bb1, 0.0f);
                uint32_t hi, lo;
                char* rp0 = smem + OFF_A2 + (mrow + 16 * h + rA) * ASTR2;
                char* rp1 = rp0 + 8 * ASTR2;
                split_pack(h00, h01, hi, lo);
                *(uint32_t*)(rp0 + c0 * 2) = hi;  *(uint32_t*)(rp0 + (80 + c0) * 2) = lo;
                split_pack(h10, h11, hi, lo);
                *(uint32_t*)(rp1 + c0 * 2) = hi;  *(uint32_t*)(rp1 + (80 + c0) * 2) = lo;
            }
        }
        __syncthreads();   // bar2: A2 complete; also proves all mmaA A1-reads done

        // ---- phase B: O[128x64], warp m32xn32, 15 k-steps ----
        float acc2[2][4][4];
        #pragma unroll
        for (int h = 0; h < 2; h++)
            #pragma unroll
            for (int j = 0; j < 4; j++)
                #pragma unroll
                for (int q = 0; q < 4; q++) acc2[h][j][q] = 0.0f;

        {
            const uint32_t aBase0 = sb + OFF_A2 + (mrow + aRow) * ASTR2 + aKof * 2;
            const uint32_t aBase1 = aBase0 + 16 * ASTR2;
            const uint32_t bBase0 = sb + OFF_B2 + (ncolB + bRow4)      * BSTR2 + bKof4 * 2;
            const uint32_t bBase1 = sb + OFF_B2 + (ncolB + 16 + bRow4) * BSTR2 + bKof4 * 2;

            #pragma unroll
            for (int s = 0; s < 15; s++) {
                const int t  = (s < 5) ? 0 : ((s < 10) ? 1 : 2);
                const int sk = s - ((t == 1) ? 5 : ((t == 2) ? 10 : 0));
                const int kA = (((t == 1) ? 80 : 0) + sk * 16) * 2;
                const int kB = (((t == 2) ? 80 : 0) + sk * 16) * 2;
                uint32_t a0, a1, a2, a3, c0, c1, c2, c3, q0, q1, q2, q3;
                ldsm_x4(a0, a1, a2, a3, aBase0 + kA);
                ldsm_x4(c0, c1, c2, c3, aBase1 + kA);
                ldsm_x4(q0, q1, q2, q3, bBase0 + kB);
                mma16816(acc2[0][0], a0, a1, a2, a3, q0, q2);
                mma16816(acc2[1][0], c0, c1, c2, c3, q0, q2);
                mma16816(acc2[0][1], a0, a1, a2, a3, q1, q3);
                mma16816(acc2[1][1], c0, c1, c2, c3, q1, q3);
                ldsm_x4(q0, q1, q2, q3, bBase1 + kB);
                mma16816(acc2[0][2], a0, a1, a2, a3, q0, q2);
                mma16816(acc2[1][2], c0, c1, c2, c3, q0, q2);
                mma16816(acc2[0][3], a0, a1, a2, a3, q1, q3);
                mma16816(acc2[1][3], c0, c1, c2, c3, q1, q3);
            }
        }

        // ---- epilogue B: tanh(+b2) -> direct STG.64 ----
        #pragma unroll
        for (int h = 0; h < 2; h++) {
            const int gr0 = e0 + mrow + 16 * h + rA;
            const int gr1 = gr0 + 8;
            #pragma unroll
            for (int j = 0; j < 4; j++) {
                const int c0 = ncolB + 8 * j + cc;
                const float bb0 = b2s[c0], bb1 = b2s[c0 + 1];
                if (gr0 < E) {
                    float2 v = make_float2(fast_tanh(acc2[h][j][0] + bb0),
                                           fast_tanh(acc2[h][j][1] + bb1));
                    *(float2*)(out + (size_t)gr0 * 64 + c0) = v;
                }
                if (gr1 < E) {
                    float2 v = make_float2(fast_tanh(acc2[h][j][2] + bb0),
                                           fast_tanh(acc2[h][j][3] + bb1));
                    *(float2*)(out + (size_t)gr1 * 64 + c0) = v;
                }
            }
        }
        // next iteration's STS(t+1) safe: bar2 proved all mmaA(t) A1-reads done.
    }
}

extern "C" void kernel_launch(void* const* d_in, const int* in_sizes, int n_in,
                              void* d_out, int out_size) {
    const float* dstf = (const float*)d_in[0];
    const float* dsth = (const float*)d_in[1];
    const float* srcf = (const float*)d_in[2];
    const float* srch = (const float*)d_in[3];
    const float* ef   = (const float*)d_in[4];
    const float* W1   = (const float*)d_in[5];
    const float* b1   = (const float*)d_in[6];
    const float* W2   = (const float*)d_in[7];
    const float* b2   = (const float*)d_in[8];
    float* out = (float*)d_out;
    const int E = in_sizes[4];
    (void)n_in; (void)out_size;

    cudaFuncSetAttribute(edge_mlp_mma,
                         cudaFuncAttributeMaxDynamicSharedMemorySize, SMEM_TOTAL);
    int sms = 148;
    cudaDeviceGetAttribute(&sms, cudaDevAttrMultiProcessorCount, 0);

    edge_mlp_mma<<<sms, THREADS, SMEM_TOTAL>>>(
        dstf, dsth, srcf, srch, ef, W1, b1, W2, b2, out, E);
}